// round 2
// baseline (speedup 1.0000x reference)
#include <cuda_runtime.h>
#include <cuda_bf16.h>

// Problem constants
#define IN_C   64
#define IMG_H  256
#define IMG_W  256
#define KSZ    3
#define OUT_C  128
#define OUT_H  254
#define OUT_W  254

// Tiling
#define TILE_H   32     // output rows per block
#define TILE_W   32     // output cols per block
#define OC_TILE  8      // output channels per block
#define C_CHUNK  4      // input channels per smem stage
#define TPW      4      // output cols per thread (threads: 8 in w, 32 in h)

#define W_ELEMS (OC_TILE * C_CHUNK * KSZ * KSZ)   // 288

__global__ __launch_bounds__(256, 3)
void conv3x3_kernel(const float* __restrict__ x,
                    const float* __restrict__ w,
                    const float* __restrict__ bias,
                    float* __restrict__ out)
{
    __shared__ float s_in[C_CHUNK][TILE_H + 2][TILE_W + 2];   // 4*34*34 floats
    __shared__ float s_w[OC_TILE][C_CHUNK][KSZ * KSZ];        // 288 floats

    const int tid = threadIdx.x;
    const int tw  = tid & 7;          // 0..7
    const int th  = tid >> 3;         // 0..31

    const int bw  = blockIdx.x;       // 0..7
    const int bh  = blockIdx.y;       // 0..7
    const int boc = blockIdx.z;       // 0..15

    const int oh = bh * TILE_H + th;          // output row this thread computes
    const int ow0 = bw * TILE_W + tw * TPW;   // first output col
    const int oc0 = boc * OC_TILE;

    float acc[OC_TILE][TPW];
#pragma unroll
    for (int o = 0; o < OC_TILE; o++) {
        const float b = bias[oc0 + o];
#pragma unroll
        for (int p = 0; p < TPW; p++) acc[o][p] = b;
    }

    const int in_row0 = bh * TILE_H;   // top input row of halo tile
    const int in_col0 = bw * TILE_W;   // left input col of halo tile

    const int HALO_ELEMS = (TILE_H + 2) * (TILE_W + 2);       // 1156 per channel

    for (int ic0 = 0; ic0 < IN_C; ic0 += C_CHUNK) {
        __syncthreads();

        // ---- load input halo tile (C_CHUNK x 34 x 34) ----
#pragma unroll 1
        for (int c = 0; c < C_CHUNK; c++) {
            const float* xc = x + (size_t)(ic0 + c) * (IMG_H * IMG_W);
            for (int i = tid; i < HALO_ELEMS; i += 256) {
                const int r  = i / (TILE_W + 2);
                const int cc = i - r * (TILE_W + 2);
                const int ih = in_row0 + r;
                const int iw = in_col0 + cc;
                float v = 0.0f;
                if (ih < IMG_H && iw < IMG_W)
                    v = xc[ih * IMG_W + iw];
                s_in[c][r][cc] = v;
            }
        }

        // ---- load weights (OC_TILE x C_CHUNK x 9 = 288 entries, 256 threads) ----
        for (int i = tid; i < W_ELEMS; i += 256) {
            const int o = i / (C_CHUNK * KSZ * KSZ);
            const int rem = i - o * (C_CHUNK * KSZ * KSZ);
            const int c = rem / (KSZ * KSZ);
            const int k = rem - c * (KSZ * KSZ);
            s_w[o][c][k] = w[(size_t)(oc0 + o) * (IN_C * KSZ * KSZ)
                             + (size_t)(ic0 + c) * (KSZ * KSZ) + k];
        }

        __syncthreads();

        // ---- compute ----
#pragma unroll
        for (int c = 0; c < C_CHUNK; c++) {
            // load the 3x6 input patch this thread needs into registers
            float r[3][TPW + 2];
#pragma unroll
            for (int kh = 0; kh < 3; kh++)
#pragma unroll
                for (int j = 0; j < TPW + 2; j++)
                    r[kh][j] = s_in[c][th + kh][tw * TPW + j];

#pragma unroll
            for (int o = 0; o < OC_TILE; o++) {
#pragma unroll
                for (int kh = 0; kh < 3; kh++) {
#pragma unroll
                    for (int kw = 0; kw < 3; kw++) {
                        const float wv = s_w[o][c][kh * 3 + kw];
#pragma unroll
                        for (int p = 0; p < TPW; p++)
                            acc[o][p] = fmaf(r[kh][p + kw], wv, acc[o][p]);
                    }
                }
            }
        }
    }

    // ---- store ----
    if (oh < OUT_H) {
#pragma unroll
        for (int o = 0; o < OC_TILE; o++) {
            float* orow = out + (size_t)(oc0 + o) * (OUT_H * OUT_W) + (size_t)oh * OUT_W;
#pragma unroll
            for (int p = 0; p < TPW; p++) {
                const int ow = ow0 + p;
                if (ow < OUT_W) orow[ow] = acc[o][p];
            }
        }
    }
}

extern "C" void kernel_launch(void* const* d_in, const int* in_sizes, int n_in,
                              void* d_out, int out_size)
{
    const float* x    = (const float*)d_in[0];
    const float* w    = (const float*)d_in[1];
    const float* bias = (const float*)d_in[2];
    float* out        = (float*)d_out;

    dim3 grid((OUT_W + TILE_W - 1) / TILE_W,    // 8
              (OUT_H + TILE_H - 1) / TILE_H,    // 8
              OUT_C / OC_TILE);                  // 16
    conv3x3_kernel<<<grid, 256>>>(x, w, bias, out);
}

// round 5
// speedup vs baseline: 4.3909x; 4.3909x over previous
#include <cuda_runtime.h>
#include <cuda_bf16.h>
#include <cstdint>

// ---------------- problem constants ----------------
#define IN_C   64
#define IMG_H  256
#define IMG_W  256
#define OUT_C  128
#define OUT_H  254
#define OUT_W  254
#define NPOS   (IMG_H * IMG_W)          // 65536
#define NTAPS  9
#define W_ROWS (NTAPS * OUT_C)          // 1152 rows per split
#define OUT_HW (OUT_H * OUT_W)          // 64516

// CTA tile: M=128 (all oc), N=128 (positions), K=64 per tap
#define N_TILE 128

// smem: stage = {Ah, Al, Bh, Bl} each 128x64 bf16 = 16KB
#define T_AH 0
#define T_AL 16384
#define T_BH 32768
#define T_BL 49152
#define STAGE_BYTES 65536
#define SMEM_TOTAL  (2 * STAGE_BYTES)   // 131072

// ---------------- device scratch (no allocs allowed) ----------------
__device__ __align__(1024) __nv_bfloat16 g_xh[NPOS * IN_C + 256];  // NHWC hi (+pad)
__device__ __align__(1024) __nv_bfloat16 g_xl[NPOS * IN_C + 256];  // NHWC lo (+pad)
__device__ __align__(1024) __nv_bfloat16 g_w[2 * W_ROWS * IN_C];   // [split][tap][oc][ic]

// ---------------- helpers ----------------
__device__ __forceinline__ uint32_t smem_u32(const void* p) {
    uint32_t a;
    asm("{ .reg .u64 t; cvta.to.shared.u64 t, %1; cvt.u32.u64 %0, t; }" : "=r"(a) : "l"(p));
    return a;
}
__device__ __forceinline__ uint32_t sw128(uint32_t o) {            // XOR swizzle, 16B units
    return o ^ ((o >> 3) & 0x70);
}
__device__ __forceinline__ void cp_async16(uint32_t dst, const void* src) {
    asm volatile("cp.async.cg.shared.global [%0], [%1], 16;" :: "r"(dst), "l"(src) : "memory");
}
__device__ __forceinline__ void cp_commit() {
    asm volatile("cp.async.commit_group;" ::: "memory");
}
template <int N>
__device__ __forceinline__ void cp_wait() {
    asm volatile("cp.async.wait_group %0;" :: "n"(N) : "memory");
}
__device__ __forceinline__ void ldsm4(uint32_t* r, uint32_t addr) {
    asm volatile("ldmatrix.sync.aligned.m8n8.x4.shared.b16 {%0,%1,%2,%3}, [%4];"
                 : "=r"(r[0]), "=r"(r[1]), "=r"(r[2]), "=r"(r[3]) : "r"(addr));
}
__device__ __forceinline__ void mma16816(float* d, const uint32_t* a, uint32_t b0, uint32_t b1) {
    asm volatile("mma.sync.aligned.m16n8k16.row.col.f32.bf16.bf16.f32 "
                 "{%0,%1,%2,%3}, {%4,%5,%6,%7}, {%8,%9}, {%0,%1,%2,%3};"
                 : "+f"(d[0]), "+f"(d[1]), "+f"(d[2]), "+f"(d[3])
                 : "r"(a[0]), "r"(a[1]), "r"(a[2]), "r"(a[3]), "r"(b0), "r"(b1));
}

// ---------------- prep kernels ----------------
// CHW fp32 -> NHWC bf16 hi/lo
__global__ __launch_bounds__(256) void prep_x(const float* __restrict__ x) {
    const int pos = blockIdx.x * 256 + threadIdx.x;
    uint32_t hw[32], lw[32];
#pragma unroll
    for (int ic = 0; ic < IN_C; ic += 2) {
        float v0 = x[(size_t)ic * NPOS + pos];
        float v1 = x[(size_t)(ic + 1) * NPOS + pos];
        __nv_bfloat16 h0 = __float2bfloat16(v0);
        __nv_bfloat16 h1 = __float2bfloat16(v1);
        __nv_bfloat16 l0 = __float2bfloat16(v0 - __bfloat162float(h0));
        __nv_bfloat16 l1 = __float2bfloat16(v1 - __bfloat162float(h1));
        hw[ic >> 1] = (uint32_t)__bfloat16_as_ushort(h0) | ((uint32_t)__bfloat16_as_ushort(h1) << 16);
        lw[ic >> 1] = (uint32_t)__bfloat16_as_ushort(l0) | ((uint32_t)__bfloat16_as_ushort(l1) << 16);
    }
    uint4* dh = reinterpret_cast<uint4*>(g_xh + (size_t)pos * IN_C);
    uint4* dl = reinterpret_cast<uint4*>(g_xl + (size_t)pos * IN_C);
#pragma unroll
    for (int i = 0; i < 8; i++) {
        dh[i] = make_uint4(hw[4*i], hw[4*i+1], hw[4*i+2], hw[4*i+3]);
        dl[i] = make_uint4(lw[4*i], lw[4*i+1], lw[4*i+2], lw[4*i+3]);
    }
}

// w[oc][ic][3][3] fp32 -> g_w[split][tap][oc][ic] bf16
__global__ __launch_bounds__(256) void prep_w(const float* __restrict__ w) {
    const int idx = blockIdx.x * 256 + threadIdx.x;     // < 9*128*64 = 73728
    const int tap = idx >> 13;
    const int oc  = (idx >> 6) & 127;
    const int ic  = idx & 63;
    float v = w[((size_t)oc * IN_C + ic) * NTAPS + tap];
    __nv_bfloat16 h = __float2bfloat16(v);
    __nv_bfloat16 l = __float2bfloat16(v - __bfloat162float(h));
    g_w[idx] = h;
    g_w[W_ROWS * IN_C + idx] = l;
}

// ---------------- main HMMA conv kernel ----------------
// grid (2, 254): blockIdx.x = col tile (128 wide), blockIdx.y = output row
__global__ __launch_bounds__(256, 1)
void conv_hmma(const float* __restrict__ bias, float* __restrict__ out)
{
    extern __shared__ char smem[];
    const uint32_t sbase = smem_u32(smem);
    const int tid  = threadIdx.x;
    const int lane = tid & 31;
    const int wid  = tid >> 5;
    const int wm   = wid & 1;            // m-group: 0/1 -> oc 0-63 / 64-127
    const int wn   = wid >> 1;           // n-group: 0..3 -> 32 positions each
    const int oh   = blockIdx.y;
    const int ow0  = blockIdx.x * N_TILE;

    // per-lane ldmatrix address components
    const int rowA = ((lane >> 3) & 1) * 8 + (lane & 7);   // + kbyte (lane>>4)*16
    const int kbA  = (lane >> 4) * 16;
    const int rowB = ((lane >> 4) & 1) * 8 + (lane & 7);   // + kbyte ((lane>>3)&1)*16
    const int kbB  = ((lane >> 3) & 1) * 16;

    float acc[4][4][4];
#pragma unroll
    for (int a = 0; a < 4; a++)
#pragma unroll
        for (int b = 0; b < 4; b++)
#pragma unroll
            for (int c = 0; c < 4; c++) acc[a][b][c] = 0.0f;

    // ---- stage copy: tap -> stage s ----
    auto issue_stage = [&](int tap, int s) {
        const int kh = tap / 3, kw = tap - kh * 3;
        const int y0 = (oh + kh) * IMG_W + kw + ow0;       // base position
        const __nv_bfloat16* srcs[4] = {
            g_w + (size_t)tap * OUT_C * IN_C,              // wh
            g_w + (size_t)(W_ROWS + tap * OUT_C) * IN_C,   // wl
            g_xh + (size_t)y0 * IN_C,                      // xh
            g_xl + (size_t)y0 * IN_C                       // xl
        };
        const uint32_t sb = sbase + s * STAGE_BYTES;
#pragma unroll
        for (int t = 0; t < 4; t++) {
#pragma unroll
            for (int i = 0; i < 4; i++) {
                const uint32_t chunk = tid + i * 256;      // 0..1023 (16B units)
                const uint32_t off = chunk * 16;
                cp_async16(sb + t * 16384 + sw128(off), srcs[t] + chunk * 8);
            }
        }
        cp_commit();
    };

    issue_stage(0, 0);

#pragma unroll 1
    for (int tap = 0; tap < NTAPS; tap++) {
        const int s = tap & 1;
        if (tap < NTAPS - 1) { issue_stage(tap + 1, s ^ 1); cp_wait<1>(); }
        else                 { cp_wait<0>(); }
        __syncthreads();

        const uint32_t aH = sbase + s * STAGE_BYTES + T_AH;
        const uint32_t aL = sbase + s * STAGE_BYTES + T_AL;
        const uint32_t bH = sbase + s * STAGE_BYTES + T_BH;
        const uint32_t bL = sbase + s * STAGE_BYTES + T_BL;

#pragma unroll
        for (int kc = 0; kc < 4; kc++) {
            uint32_t ah[4][4], al[4][4];
#pragma unroll
            for (int mi = 0; mi < 4; mi++) {
                const uint32_t o = (uint32_t)(wm * 64 + mi * 16 + rowA) * 128 + kc * 32 + kbA;
                const uint32_t so = sw128(o);
                ldsm4(ah[mi], aH + so);
                ldsm4(al[mi], aL + so);
            }
#pragma unroll
            for (int nj = 0; nj < 2; nj++) {
                uint32_t bh[4], bl[4];
                const uint32_t o = (uint32_t)(wn * 32 + nj * 16 + rowB) * 128 + kc * 32 + kbB;
                const uint32_t so = sw128(o);
                ldsm4(bh, bH + so);
                ldsm4(bl, bL + so);
#pragma unroll
                for (int mi = 0; mi < 4; mi++) {
                    mma16816(acc[mi][nj*2],   ah[mi], bh[0], bh[1]);   // wh*xh
                    mma16816(acc[mi][nj*2+1], ah[mi], bh[2], bh[3]);
                    mma16816(acc[mi][nj*2],   al[mi], bh[0], bh[1]);   // wl*xh
                    mma16816(acc[mi][nj*2+1], al[mi], bh[2], bh[3]);
                    mma16816(acc[mi][nj*2],   ah[mi], bl[0], bl[1]);   // wh*xl
                    mma16816(acc[mi][nj*2+1], ah[mi], bl[2], bl[3]);
                }
            }
        }
        __syncthreads();    // stage s may be overwritten next+1 iteration
    }

    // ---- epilogue: direct gmem stores ----
#pragma unroll
    for (int mi = 0; mi < 4; mi++) {
        const int oc0 = wm * 64 + mi * 16 + (lane >> 2);
        const float b0 = bias[oc0];
        const float b1 = bias[oc0 + 8];
#pragma unroll
        for (int ni = 0; ni < 4; ni++) {
            const int owp = ow0 + wn * 32 + ni * 8 + (lane & 3) * 2;
            if (owp < OUT_W) {
                float2 v0 = make_float2(acc[mi][ni][0] + b0, acc[mi][ni][1] + b0);
                float2 v1 = make_float2(acc[mi][ni][2] + b1, acc[mi][ni][3] + b1);
                *reinterpret_cast<float2*>(out + (size_t)oc0 * OUT_HW + oh * OUT_W + owp) = v0;
                *reinterpret_cast<float2*>(out + (size_t)(oc0 + 8) * OUT_HW + oh * OUT_W + owp) = v1;
            }
        }
    }
}

// ---------------- launch ----------------
extern "C" void kernel_launch(void* const* d_in, const int* in_sizes, int n_in,
                              void* d_out, int out_size)
{
    const float* x    = (const float*)d_in[0];
    const float* w    = (const float*)d_in[1];
    const float* bias = (const float*)d_in[2];
    float* out        = (float*)d_out;

    cudaFuncSetAttribute(conv_hmma, cudaFuncAttributeMaxDynamicSharedMemorySize, SMEM_TOTAL);

    prep_x<<<NPOS / 256, 256>>>(x);
    prep_w<<<(NTAPS * OUT_C * IN_C) / 256, 256>>>(w);
    conv_hmma<<<dim3(2, OUT_H), 256, SMEM_TOTAL>>>(bias, out);
}

// round 6
// speedup vs baseline: 9.7590x; 2.2226x over previous
#include <cuda_runtime.h>
#include <cuda_fp16.h>
#include <cstdint>

// ---------------- problem constants ----------------
#define IN_C   64
#define IMG_H  256
#define IMG_W  256
#define OUT_C  128
#define OUT_H  254
#define OUT_W  254
#define NPOS   (IMG_H * IMG_W)          // 65536
#define NTAPS  9
#define OUT_HW (OUT_H * OUT_W)

// CTA tile: M=128 (all oc), N=128 (positions), K=64 per tap
#define N_TILE 128

// smem layout
#define SM_A        0                   // 2 stages x 16KB (w tap tile, 128x64 fp16)
#define A_STAGE     16384
#define SM_B        32768               // 3 strips (kh) x 136 rows x 128B
#define STRIP_STRIDE 17408              // 136*128, 1024-aligned
#define STRIP_LOAD_ROWS 130
#define SMEM_TOTAL  (32768 + 3 * STRIP_STRIDE)   // 84992

// ---------------- device scratch (no allocs allowed) ----------------
__device__ __align__(1024) __half g_x[NPOS * IN_C + 256];   // NHWC fp16 (+4 pos pad)
__device__ __align__(1024) __half g_w[NTAPS * OUT_C * IN_C];// [tap][oc][ic] fp16

// ---------------- helpers ----------------
__device__ __forceinline__ uint32_t smem_u32(const void* p) {
    uint32_t a;
    asm("{ .reg .u64 t; cvta.to.shared.u64 t, %1; cvt.u32.u64 %0, t; }" : "=r"(a) : "l"(p));
    return a;
}
__device__ __forceinline__ uint32_t sw128(uint32_t o) { return o ^ ((o >> 3) & 0x70); }
__device__ __forceinline__ void cp_async16(uint32_t dst, const void* src) {
    asm volatile("cp.async.cg.shared.global [%0], [%1], 16;" :: "r"(dst), "l"(src) : "memory");
}
__device__ __forceinline__ void cp_commit() {
    asm volatile("cp.async.commit_group;" ::: "memory");
}
template <int N>
__device__ __forceinline__ void cp_wait() {
    asm volatile("cp.async.wait_group %0;" :: "n"(N) : "memory");
}
__device__ __forceinline__ void ldsm4(uint32_t* r, uint32_t addr) {
    asm volatile("ldmatrix.sync.aligned.m8n8.x4.shared.b16 {%0,%1,%2,%3}, [%4];"
                 : "=r"(r[0]), "=r"(r[1]), "=r"(r[2]), "=r"(r[3]) : "r"(addr));
}
__device__ __forceinline__ void mma16816(float* d, const uint32_t* a, uint32_t b0, uint32_t b1) {
    asm volatile("mma.sync.aligned.m16n8k16.row.col.f32.f16.f16.f32 "
                 "{%0,%1,%2,%3}, {%4,%5,%6,%7}, {%8,%9}, {%0,%1,%2,%3};"
                 : "+f"(d[0]), "+f"(d[1]), "+f"(d[2]), "+f"(d[3])
                 : "r"(a[0]), "r"(a[1]), "r"(a[2]), "r"(a[3]), "r"(b0), "r"(b1));
}

// ---------------- prep kernels ----------------
// CHW fp32 -> NHWC fp16 via smem transpose. Block = 32 pos x 64 ic. Grid 2048.
__global__ __launch_bounds__(256) void prep_x(const float* __restrict__ x) {
    __shared__ float s[IN_C][33];
    const int tid  = threadIdx.x;
    const int pos0 = blockIdx.x * 32;

    // coalesced read: each thread 8 values
#pragma unroll
    for (int r = 0; r < 8; r++) {
        const int ic = r * 8 + (tid >> 5);
        const int pl = tid & 31;
        s[ic][pl] = x[(size_t)ic * NPOS + pos0 + pl];
    }
    __syncthreads();

    // coalesced write: thread -> (pos = tid>>3, ic0 = (tid&7)*8), 8 fp16 = 16B
    const int pl  = tid >> 3;
    const int ic0 = (tid & 7) * 8;
    uint32_t pk[4];
#pragma unroll
    for (int j = 0; j < 4; j++) {
        __half h0 = __float2half(s[ic0 + 2*j][pl]);
        __half h1 = __float2half(s[ic0 + 2*j + 1][pl]);
        pk[j] = (uint32_t)__half_as_ushort(h0) | ((uint32_t)__half_as_ushort(h1) << 16);
    }
    *reinterpret_cast<uint4*>(g_x + (size_t)(pos0 + pl) * IN_C + ic0) =
        make_uint4(pk[0], pk[1], pk[2], pk[3]);
}

// w[oc][ic][3][3] fp32 -> g_w[tap][oc][ic] fp16
__global__ __launch_bounds__(256) void prep_w(const float* __restrict__ w) {
    const int idx = blockIdx.x * 256 + threadIdx.x;     // < 9*128*64 = 73728
    const int tap = idx >> 13;
    const int oc  = (idx >> 6) & 127;
    const int ic  = idx & 63;
    g_w[idx] = __float2half(w[((size_t)oc * IN_C + ic) * NTAPS + tap]);
}

// ---------------- main HMMA conv kernel ----------------
// grid (2, 254): blockIdx.x = col tile (128 wide), blockIdx.y = output row
__global__ __launch_bounds__(256, 2)
void conv_hmma(const float* __restrict__ bias, float* __restrict__ out)
{
    extern __shared__ char smem[];
    const uint32_t sbase = smem_u32(smem);
    const int tid  = threadIdx.x;
    const int lane = tid & 31;
    const int wid  = tid >> 5;
    const int wm   = wid & 1;            // m-group: oc 0-63 / 64-127
    const int wn   = wid >> 1;           // n-group: 0..3, 32 positions each
    const int oh   = blockIdx.y;
    const int ow0  = blockIdx.x * N_TILE;

    // ldmatrix per-lane address components (same mapping as validated R5 kernel)
    const int rowA = ((lane >> 3) & 1) * 8 + (lane & 7);
    const int kbA  = (lane >> 4) * 16;
    const int rowB = ((lane >> 4) & 1) * 8 + (lane & 7);
    const int kbB  = ((lane >> 3) & 1) * 16;

    float acc[4][4][4];
#pragma unroll
    for (int a = 0; a < 4; a++)
#pragma unroll
        for (int b = 0; b < 4; b++)
#pragma unroll
            for (int c = 0; c < 4; c++) acc[a][b][c] = 0.0f;

    // ---- load the 3 B strips (once) ----
    auto issue_strips = [&]() {
        for (int i = tid; i < 3 * 1040; i += 256) {               // 1040 16B-chunks/strip
            const int strip = i / 1040;
            const int c     = i - strip * 1040;
            const int y0    = (oh + strip) * IMG_W + ow0;
            cp_async16(sbase + SM_B + strip * STRIP_STRIDE + sw128((uint32_t)c * 16),
                       g_x + (size_t)y0 * IN_C + c * 8);
        }
    };
    // ---- load one weight tap tile into a stage ----
    auto issue_A = [&](int tap, int s) {
        const __half* src = g_w + (size_t)tap * OUT_C * IN_C;
        const uint32_t sb = sbase + SM_A + s * A_STAGE;
#pragma unroll
        for (int i = 0; i < 4; i++) {
            const uint32_t chunk = tid + i * 256;                 // 0..1023
            cp_async16(sb + sw128(chunk * 16), src + chunk * 8);
        }
    };

    issue_strips();
    issue_A(0, 0);
    cp_commit();            // g0: strips + A0
    issue_A(1, 1);
    cp_commit();            // g1: A1

#pragma unroll 1
    for (int t = 0; t < NTAPS; t++) {
        if (t < NTAPS - 1) cp_wait<1>(); else cp_wait<0>();
        __syncthreads();

        const int kh = t / 3;
        const int kw = t - kh * 3;
        const uint32_t aBase = sbase + SM_A + (t & 1) * A_STAGE;
        const uint32_t bBase = sbase + SM_B + kh * STRIP_STRIDE;

#pragma unroll
        for (int kc = 0; kc < 4; kc++) {
            uint32_t a[4][4];
#pragma unroll
            for (int mi = 0; mi < 4; mi++) {
                const uint32_t o = (uint32_t)(wm * 64 + mi * 16 + rowA) * 128 + kc * 32 + kbA;
                ldsm4(a[mi], aBase + sw128(o));
            }
#pragma unroll
            for (int nj = 0; nj < 2; nj++) {
                uint32_t b[4];
                const uint32_t brow = (uint32_t)(kw + wn * 32 + nj * 16 + rowB);
                const uint32_t o = brow * 128 + kc * 32 + kbB;
                ldsm4(b, bBase + sw128(o));
#pragma unroll
                for (int mi = 0; mi < 4; mi++) {
                    mma16816(acc[mi][nj * 2],     a[mi], b[0], b[1]);
                    mma16816(acc[mi][nj * 2 + 1], a[mi], b[2], b[3]);
                }
            }
        }
        __syncthreads();
        if (t + 2 < NTAPS) { issue_A(t + 2, t & 1); cp_commit(); }
    }

    // ---- epilogue: direct gmem stores ----
#pragma unroll
    for (int mi = 0; mi < 4; mi++) {
        const int oc0 = wm * 64 + mi * 16 + (lane >> 2);
        const float b0 = bias[oc0];
        const float b1 = bias[oc0 + 8];
#pragma unroll
        for (int ni = 0; ni < 4; ni++) {
            const int owp = ow0 + wn * 32 + ni * 8 + (lane & 3) * 2;
            if (owp < OUT_W) {
                float2 v0 = make_float2(acc[mi][ni][0] + b0, acc[mi][ni][1] + b0);
                float2 v1 = make_float2(acc[mi][ni][2] + b1, acc[mi][ni][3] + b1);
                *reinterpret_cast<float2*>(out + (size_t)oc0 * OUT_HW + oh * OUT_W + owp) = v0;
                *reinterpret_cast<float2*>(out + (size_t)(oc0 + 8) * OUT_HW + oh * OUT_W + owp) = v1;
            }
        }
    }
}

// ---------------- launch ----------------
extern "C" void kernel_launch(void* const* d_in, const int* in_sizes, int n_in,
                              void* d_out, int out_size)
{
    const float* x    = (const float*)d_in[0];
    const float* w    = (const float*)d_in[1];
    const float* bias = (const float*)d_in[2];
    float* out        = (float*)d_out;

    cudaFuncSetAttribute(conv_hmma, cudaFuncAttributeMaxDynamicSharedMemorySize, SMEM_TOTAL);

    prep_x<<<NPOS / 32, 256>>>(x);
    prep_w<<<(NTAPS * OUT_C * IN_C) / 256, 256>>>(w);
    conv_hmma<<<dim3(2, OUT_H), 256, SMEM_TOTAL>>>(bias, out);
}